// round 2
// baseline (speedup 1.0000x reference)
#include <cuda_runtime.h>

// RVQ: x [16,2048,128] f32, codebooks [8,1024,128] f32
// out (float32): indices [B*N*Q] ++ quantized [B*N*D] ++ commits [Q]

#define TOKENS   32768     // B*N
#define DDIM     128
#define KCODES   1024
#define QSTAGES  8
#define BM       128       // tokens per block
#define BKT      128       // codes per smem tile
#define NTHREADS 256
#define ASTRIDE  132       // 128 + 4 pad (keeps float4 alignment, breaks bank conflicts)
#define NBLOCKS  (TOKENS / BM)   // 256

// Scratch (no allocations allowed): residual chain + per-stage data
__device__ float g_res[TOKENS * DDIM];          // 16 MB
__device__ float g_c2[QSTAGES * KCODES];        // ||c||^2
__device__ float g_partial[QSTAGES * NBLOCKS];  // deterministic commit partials

// ---------------------------------------------------------------------------
// ||c||^2 for all Q*K codes. One warp per code.
// ---------------------------------------------------------------------------
__global__ void c2_kernel(const float* __restrict__ cb) {
    int warp = (blockIdx.x * blockDim.x + threadIdx.x) >> 5;   // 0..8191
    int lane = threadIdx.x & 31;
    const float4* row = (const float4*)(cb + (size_t)warp * DDIM);
    float4 v = row[lane];
    float s = v.x * v.x + v.y * v.y + v.z * v.z + v.w * v.w;
    #pragma unroll
    for (int o = 16; o > 0; o >>= 1) s += __shfl_down_sync(0xffffffffu, s, o);
    if (lane == 0) g_c2[warp] = s;
}

// ---------------------------------------------------------------------------
// One RVQ stage: distances (GEMM) + argmin + residual update + commit partial.
// BM=128 tokens/block, all K=1024 codes streamed in 8 tiles of 128.
// Thread microtile: 8 tokens x 8 codes (64 fp32 accumulators).
// ---------------------------------------------------------------------------
extern __shared__ float smem[];

__global__ __launch_bounds__(NTHREADS, 1)
void stage_kernel(const float* __restrict__ x,         // original input
                  const float* __restrict__ cb_all,    // [Q,K,D]
                  float* __restrict__ out,
                  int stage, int is_last) {
    float* As = smem;                       // [D][ASTRIDE] transposed residual
    float* Bs = smem + DDIM * ASTRIDE;      // [D][ASTRIDE] transposed code tile
    // overlays on Bs (only used after last compute tile, behind __syncthreads)
    float* redv   = Bs;                     // [16][128] per-group best dist
    int*   redi   = (int*)(Bs + 2048);      // [16][128] per-group best idx
    int*   chosen = (int*)(Bs + 4096);      // [128] final argmin per token

    const float*  src = (stage == 0) ? x : (const float*)g_res;
    const float*  cb  = cb_all + (size_t)stage * KCODES * DDIM;
    const float4* cb4 = (const float4*)cb;
    const float*  c2  = g_c2 + stage * KCODES;

    const int tid  = threadIdx.x;
    const int tok0 = blockIdx.x * BM;

    // ---- load A tile (residuals for 128 tokens), transposed into smem ----
    const float4* src4 = (const float4*)src + (size_t)tok0 * (DDIM / 4);
    for (int f = tid; f < BM * (DDIM / 4); f += NTHREADS) {
        int t = f >> 5, d4 = f & 31;
        float4 v = src4[t * 32 + d4];
        As[(d4 * 4 + 0) * ASTRIDE + t] = v.x;
        As[(d4 * 4 + 1) * ASTRIDE + t] = v.y;
        As[(d4 * 4 + 2) * ASTRIDE + t] = v.z;
        As[(d4 * 4 + 3) * ASTRIDE + t] = v.w;
    }

    const int r  = tid & 15;   // token group (8 tokens each)
    const int cg = tid >> 4;   // code group  (8 codes each)

    float best[8];
    int   bidx[8];
    #pragma unroll
    for (int i = 0; i < 8; i++) { best[i] = 3.4e38f; bidx[i] = 0; }

    for (int kt = 0; kt < KCODES / BKT; kt++) {
        __syncthreads();   // previous tile (and initial A load) complete
        // ---- load B tile (128 codes), transposed ----
        for (int f = tid; f < BKT * (DDIM / 4); f += NTHREADS) {
            int kl = f >> 5, d4 = f & 31;
            float4 v = cb4[(size_t)(kt * BKT + kl) * 32 + d4];
            Bs[(d4 * 4 + 0) * ASTRIDE + kl] = v.x;
            Bs[(d4 * 4 + 1) * ASTRIDE + kl] = v.y;
            Bs[(d4 * 4 + 2) * ASTRIDE + kl] = v.z;
            Bs[(d4 * 4 + 3) * ASTRIDE + kl] = v.w;
        }
        __syncthreads();

        float acc[8][8];
        #pragma unroll
        for (int i = 0; i < 8; i++)
            #pragma unroll
            for (int j = 0; j < 8; j++) acc[i][j] = 0.f;

        #pragma unroll 2
        for (int d = 0; d < DDIM; d++) {
            float a[8], b[8];
            float4 t0 = *(const float4*)&As[d * ASTRIDE + r * 8];
            float4 t1 = *(const float4*)&As[d * ASTRIDE + r * 8 + 4];
            a[0]=t0.x; a[1]=t0.y; a[2]=t0.z; a[3]=t0.w;
            a[4]=t1.x; a[5]=t1.y; a[6]=t1.z; a[7]=t1.w;
            float4 u0 = *(const float4*)&Bs[d * ASTRIDE + cg * 8];
            float4 u1 = *(const float4*)&Bs[d * ASTRIDE + cg * 8 + 4];
            b[0]=u0.x; b[1]=u0.y; b[2]=u0.z; b[3]=u0.w;
            b[4]=u1.x; b[5]=u1.y; b[6]=u1.z; b[7]=u1.w;
            #pragma unroll
            for (int i = 0; i < 8; i++)
                #pragma unroll
                for (int j = 0; j < 8; j++)
                    acc[i][j] += a[i] * b[j];
        }

        // ---- running argmin over this tile's codes (ascending j: first-occurrence) ----
        #pragma unroll
        for (int j = 0; j < 8; j++) {
            int code = kt * BKT + cg * 8 + j;
            float cc = __ldg(&c2[code]);
            #pragma unroll
            for (int i = 0; i < 8; i++) {
                float dd = cc - 2.f * acc[i][j];
                if (dd < best[i]) { best[i] = dd; bidx[i] = code; }
            }
        }
    }

    // ---- cross-group argmin reduction ----
    __syncthreads();   // compute done; safe to overlay Bs
    #pragma unroll
    for (int i = 0; i < 8; i++) {
        redv[cg * 128 + r * 8 + i] = best[i];
        redi[cg * 128 + r * 8 + i] = bidx[i];
    }
    __syncthreads();
    if (tid < BM) {
        float bv = redv[tid];
        int   bi = redi[tid];
        #pragma unroll
        for (int c = 1; c < 16; c++) {
            float v  = redv[c * 128 + tid];
            int   ci = redi[c * 128 + tid];
            if (v < bv || (v == bv && ci < bi)) { bv = v; bi = ci; }
        }
        chosen[tid] = bi;
        out[(size_t)(tok0 + tid) * QSTAGES + stage] = (float)bi;   // index as f32
    }
    __syncthreads();

    // ---- residual update, commit partial, optional quantized output ----
    float4*       res4 = (float4*)g_res + (size_t)tok0 * 32;
    const float4* x4   = (const float4*)x + (size_t)tok0 * 32;
    float4*       q4   = (float4*)(out + (size_t)TOKENS * QSTAGES) + (size_t)tok0 * 32;

    float psum = 0.f;
    for (int f = tid; f < BM * 32; f += NTHREADS) {
        int t = f >> 5, d4 = f & 31;
        int k = chosen[t];
        float4 cv = cb4[(size_t)k * 32 + d4];
        float4 nv;
        nv.x = As[(d4 * 4 + 0) * ASTRIDE + t] - cv.x;
        nv.y = As[(d4 * 4 + 1) * ASTRIDE + t] - cv.y;
        nv.z = As[(d4 * 4 + 2) * ASTRIDE + t] - cv.z;
        nv.w = As[(d4 * 4 + 3) * ASTRIDE + t] - cv.w;
        res4[t * 32 + d4] = nv;
        psum += nv.x * nv.x + nv.y * nv.y + nv.z * nv.z + nv.w * nv.w;
        if (is_last) {
            float4 xv = x4[t * 32 + d4];
            float4 qv;
            qv.x = xv.x - nv.x; qv.y = xv.y - nv.y;
            qv.z = xv.z - nv.z; qv.w = xv.w - nv.w;
            q4[t * 32 + d4] = qv;
        }
    }
    // deterministic block reduction (no float atomics -> graph-replay stable)
    int lane = tid & 31, w = tid >> 5;
    #pragma unroll
    for (int o = 16; o > 0; o >>= 1) psum += __shfl_down_sync(0xffffffffu, psum, o);
    if (lane == 0) redv[w] = psum;
    __syncthreads();
    if (tid == 0) {
        float s = 0.f;
        #pragma unroll
        for (int w2 = 0; w2 < 8; w2++) s += redv[w2];
        g_partial[stage * NBLOCKS + blockIdx.x] = s;
    }
}

// ---------------------------------------------------------------------------
// Commit losses: fixed-order sum of block partials (deterministic).
// ---------------------------------------------------------------------------
__global__ void finish_kernel(float* __restrict__ out) {
    int q = threadIdx.x;
    if (q < QSTAGES) {
        float s = 0.f;
        for (int b = 0; b < NBLOCKS; b++) s += g_partial[q * NBLOCKS + b];
        out[(size_t)TOKENS * QSTAGES + (size_t)TOKENS * DDIM + q] =
            s / (float)(TOKENS * DDIM);
    }
}

extern "C" void kernel_launch(void* const* d_in, const int* in_sizes, int n_in,
                              void* d_out, int out_size) {
    const float* x  = (const float*)d_in[0];
    const float* cb = (const float*)d_in[1];
    float* out = (float*)d_out;

    size_t shmem = 2 * DDIM * ASTRIDE * sizeof(float);   // 135168 B
    cudaFuncSetAttribute(stage_kernel,
                         cudaFuncAttributeMaxDynamicSharedMemorySize, (int)shmem);

    // ||c||^2 for all stages (8192 codes, warp per code)
    c2_kernel<<<1024, 256>>>(cb);

    for (int s = 0; s < QSTAGES; s++) {
        stage_kernel<<<NBLOCKS, NTHREADS, shmem>>>(x, cb, out, s,
                                                   (s == QSTAGES - 1) ? 1 : 0);
    }
    finish_kernel<<<1, 32>>>(out);
}

// round 3
// speedup vs baseline: 1.2991x; 1.2991x over previous
#include <cuda_runtime.h>
#include <cstdint>

// RVQ: x [16,2048,128] f32, codebooks [8,1024,128] f32
// out (float32): indices [B*N*Q] ++ quantized [B*N*D] ++ commits [Q]

#define TOKENS   32768
#define DDIM     128
#define NCH      32          // float4 chunks per row
#define KCODES   1024
#define QSTAGES  8
#define BM       128
#define BKT      128
#define NTHREADS 256
#define NBLOCKS  (TOKENS / BM)   // 256

__device__ float g_res[TOKENS * DDIM];
__device__ float g_c2[QSTAGES * KCODES];
__device__ float g_partial[QSTAGES * NBLOCKS];

// ---------------------------------------------------------------------------
__device__ __forceinline__ void cp16(uint32_t dst, const void* src) {
    asm volatile("cp.async.cg.shared.global [%0], [%1], 16;" :: "r"(dst), "l"(src));
}
__device__ __forceinline__ void cp_commit() { asm volatile("cp.async.commit_group;"); }
template<int N> __device__ __forceinline__ void cp_wait() {
    asm volatile("cp.async.wait_group %0;" :: "n"(N) : "memory");
}
// packed fp32x2 FMA (Blackwell): d = a*b + c on both lanes
__device__ __forceinline__ unsigned long long ffma2(unsigned long long a,
                                                    unsigned long long b,
                                                    unsigned long long c) {
    unsigned long long d;
    asm("fma.rn.f32x2 %0, %1, %2, %3;" : "=l"(d) : "l"(a), "l"(b), "l"(c));
    return d;
}
__device__ __forceinline__ float pairsum(unsigned long long v) {
    float lo, hi;
    asm("mov.b64 {%0, %1}, %2;" : "=f"(lo), "=f"(hi) : "l"(v));
    return lo + hi;
}

// ---------------------------------------------------------------------------
// ||c||^2 for all Q*K codes. One warp per code.
// ---------------------------------------------------------------------------
__global__ void c2_kernel(const float* __restrict__ cb) {
    int warp = (blockIdx.x * blockDim.x + threadIdx.x) >> 5;
    int lane = threadIdx.x & 31;
    const float4* row = (const float4*)(cb + (size_t)warp * DDIM);
    float4 v = row[lane];
    float s = v.x * v.x + v.y * v.y + v.z * v.z + v.w * v.w;
    #pragma unroll
    for (int o = 16; o > 0; o >>= 1) s += __shfl_down_sync(0xffffffffu, s, o);
    if (lane == 0) g_c2[warp] = s;
}

// ---------------------------------------------------------------------------
// One RVQ stage. CTA tile 128 tokens x 128 codes per kt, 8 kt tiles.
// Swizzled smem (chunk c stored at c ^ ((row>>2)&7)) -> conflict-free LDS.128.
// Compute with fma.rn.f32x2, pairing the two halves of each float2.
// ---------------------------------------------------------------------------
extern __shared__ float smem[];

__global__ __launch_bounds__(NTHREADS, 1)
void stage_kernel(const float* __restrict__ x,
                  const float* __restrict__ cb_all,
                  float* __restrict__ out,
                  int stage, int is_last) {
    float* As     = smem;                     // [128][128] swizzled  (64 KB)
    float* Bs0    = smem + 16384;             // tile buffer 0        (64 KB)
    float* Bs1    = smem + 32768;             // tile buffer 1        (64 KB)
    float* redv   = smem + 49152;             // [16][128]
    int*   redi   = (int*)(smem + 51200);     // [16][128]
    int*   chosen = (int*)(smem + 53248);     // [128]

    const float*  src = (stage == 0) ? x : (const float*)g_res;
    const float*  cb  = cb_all + (size_t)stage * KCODES * DDIM;
    const float4* cb4 = (const float4*)cb;
    const float*  c2  = g_c2 + stage * KCODES;

    const int tid  = threadIdx.x;
    const int tok0 = blockIdx.x * BM;
    const int lane = tid & 31, wid = tid >> 5;
    const int warp_t = wid & 1, warp_c = wid >> 1;   // 2 x 4 warps
    const int t8 = lane & 7, c4 = lane >> 3;          // 8 x 4 lanes

    // ---- async fill: A tile + B tile 0 (swizzled destinations) ----
    {
        const float4* s4  = (const float4*)src + (size_t)tok0 * NCH;
        uint32_t asb = (uint32_t)__cvta_generic_to_shared(As);
        uint32_t bsb = (uint32_t)__cvta_generic_to_shared(Bs0);
        #pragma unroll
        for (int k = 0; k < 16; k++) {
            int f = tid + k * NTHREADS;
            int t = f >> 5, c = f & 31;
            int sw = c ^ ((t >> 2) & 7);
            cp16(asb + (uint32_t)(t * 512 + sw * 16), s4 + t * NCH + c);
            cp16(bsb + (uint32_t)(t * 512 + sw * 16), cb4 + t * NCH + c);
        }
        cp_commit();
    }

    // per-thread rows: 8 tokens, 8 codes
    const int tloc0 = warp_t * 64 + t8 * 4;
    const ulonglong2* aP[8];
    int tl[8];
    #pragma unroll
    for (int i = 0; i < 8; i++) {
        tl[i] = tloc0 + (i < 4 ? i : 32 + (i - 4));
        aP[i] = (const ulonglong2*)(As + tl[i] * DDIM);
    }
    int cloc[8];
    #pragma unroll
    for (int j = 0; j < 8; j++)
        cloc[j] = warp_c * 32 + (j < 4 ? c4 * 4 + j : 16 + c4 * 4 + (j - 4));

    float best[8]; int bidx[8];
    #pragma unroll
    for (int i = 0; i < 8; i++) { best[i] = 3.4e38f; bidx[i] = 0; }

    for (int kt = 0; kt < KCODES / BKT; kt++) {
        __syncthreads();   // everyone done with the buffer we are about to refill
        if (kt + 1 < KCODES / BKT) {
            float* Bn = ((kt + 1) & 1) ? Bs1 : Bs0;
            uint32_t bsb = (uint32_t)__cvta_generic_to_shared(Bn);
            const float4* bsrc = cb4 + (size_t)(kt + 1) * BKT * NCH;
            #pragma unroll
            for (int k = 0; k < 16; k++) {
                int f = tid + k * NTHREADS;
                int t = f >> 5, c = f & 31;
                int sw = c ^ ((t >> 2) & 7);
                cp16(bsb + (uint32_t)(t * 512 + sw * 16), bsrc + t * NCH + c);
            }
            cp_commit();
            cp_wait<1>();   // current tile (and A) ready
        } else {
            cp_wait<0>();
        }
        __syncthreads();

        const float* Bt = (kt & 1) ? Bs1 : Bs0;

        // two passes of 4 codes each (keeps accumulators at 32 ulls)
        #pragma unroll
        for (int pass = 0; pass < 2; pass++) {
            const ulonglong2* bP[4];
            #pragma unroll
            for (int jj = 0; jj < 4; jj++)
                bP[jj] = (const ulonglong2*)(Bt + cloc[pass * 4 + jj] * DDIM);
            const int cbx = (pass == 0) ? 0 : 4;   // swizzle group of this code half

            unsigned long long acc[8][4];
            #pragma unroll
            for (int i = 0; i < 8; i++)
                #pragma unroll
                for (int jj = 0; jj < 4; jj++) acc[i][jj] = 0ull;

            #pragma unroll 4
            for (int d4 = 0; d4 < NCH; d4++) {
                int ca = d4 ^ t8;
                int cbo = (d4 ^ c4) ^ cbx;
                ulonglong2 b[4];
                #pragma unroll
                for (int jj = 0; jj < 4; jj++) b[jj] = bP[jj][cbo];
                #pragma unroll
                for (int i = 0; i < 8; i++) {
                    ulonglong2 a = aP[i][ca];
                    #pragma unroll
                    for (int jj = 0; jj < 4; jj++) {
                        acc[i][jj] = ffma2(a.x, b[jj].x, acc[i][jj]);
                        acc[i][jj] = ffma2(a.y, b[jj].y, acc[i][jj]);
                    }
                }
            }

            // running argmin, ascending code order (first-occurrence semantics)
            #pragma unroll
            for (int jj = 0; jj < 4; jj++) {
                int code = kt * BKT + cloc[pass * 4 + jj];
                float cc = __ldg(&c2[code]);
                #pragma unroll
                for (int i = 0; i < 8; i++) {
                    float dd = cc - 2.f * pairsum(acc[i][jj]);
                    if (dd < best[i]) { best[i] = dd; bidx[i] = code; }
                }
            }
        }
    }

    // ---- cross-thread argmin reduction (16 contributors per token) ----
    __syncthreads();
    const int contrib = warp_c * 4 + c4;   // 0..15
    #pragma unroll
    for (int i = 0; i < 8; i++) {
        redv[contrib * 128 + tl[i]] = best[i];
        redi[contrib * 128 + tl[i]] = bidx[i];
    }
    __syncthreads();
    if (tid < BM) {
        float bv = redv[tid];
        int   bi = redi[tid];
        #pragma unroll
        for (int c = 1; c < 16; c++) {
            float v  = redv[c * 128 + tid];
            int   ci = redi[c * 128 + tid];
            if (v < bv || (v == bv && ci < bi)) { bv = v; bi = ci; }
        }
        chosen[tid] = bi;
        out[(size_t)(tok0 + tid) * QSTAGES + stage] = (float)bi;
    }
    __syncthreads();

    // ---- residual update + commit partial + optional quantized output ----
    float4*       res4 = (float4*)g_res + (size_t)tok0 * NCH;
    const float4* x4   = (const float4*)x + (size_t)tok0 * NCH;
    float4*       q4   = (float4*)(out + (size_t)TOKENS * QSTAGES) + (size_t)tok0 * NCH;

    float psum = 0.f;
    #pragma unroll
    for (int k = 0; k < 16; k++) {
        int f = tid + k * NTHREADS;
        int t = f >> 5, d4 = f & 31;
        int sw = d4 ^ ((t >> 2) & 7);
        float4 rv = *(const float4*)(As + t * DDIM + sw * 4);
        int kk = chosen[t];
        float4 cv = cb4[(size_t)kk * NCH + d4];
        float4 nv = make_float4(rv.x - cv.x, rv.y - cv.y, rv.z - cv.z, rv.w - cv.w);
        res4[t * NCH + d4] = nv;
        psum += nv.x * nv.x + nv.y * nv.y + nv.z * nv.z + nv.w * nv.w;
        if (is_last) {
            float4 xv = x4[t * NCH + d4];
            q4[t * NCH + d4] = make_float4(xv.x - nv.x, xv.y - nv.y,
                                           xv.z - nv.z, xv.w - nv.w);
        }
    }
    int ln = tid & 31, w = tid >> 5;
    #pragma unroll
    for (int o = 16; o > 0; o >>= 1) psum += __shfl_down_sync(0xffffffffu, psum, o);
    if (ln == 0) redv[w] = psum;
    __syncthreads();
    if (tid == 0) {
        float s = 0.f;
        #pragma unroll
        for (int w2 = 0; w2 < 8; w2++) s += redv[w2];
        g_partial[stage * NBLOCKS + blockIdx.x] = s;
    }
}

// ---------------------------------------------------------------------------
__global__ void finish_kernel(float* __restrict__ out) {
    int q = threadIdx.x;
    if (q < QSTAGES) {
        float s = 0.f;
        for (int b = 0; b < NBLOCKS; b++) s += g_partial[q * NBLOCKS + b];
        out[(size_t)TOKENS * QSTAGES + (size_t)TOKENS * DDIM + q] =
            s / (float)(TOKENS * DDIM);
    }
}

extern "C" void kernel_launch(void* const* d_in, const int* in_sizes, int n_in,
                              void* d_out, int out_size) {
    const float* x  = (const float*)d_in[0];
    const float* cb = (const float*)d_in[1];
    float* out = (float*)d_out;

    size_t shmem = (size_t)(53248 + 128) * sizeof(float);   // 213504 B
    cudaFuncSetAttribute(stage_kernel,
                         cudaFuncAttributeMaxDynamicSharedMemorySize, (int)shmem);

    c2_kernel<<<1024, 256>>>(cb);
    for (int s = 0; s < QSTAGES; s++) {
        stage_kernel<<<NBLOCKS, NTHREADS, shmem>>>(x, cb, out, s,
                                                   (s == QSTAGES - 1) ? 1 : 0);
    }
    finish_kernel<<<1, 32>>>(out);
}

// round 4
// speedup vs baseline: 1.3768x; 1.0597x over previous
#include <cuda_runtime.h>
#include <cstdint>

// RVQ: x [16,2048,128] f32, codebooks [8,1024,128] f32
// out (float32): indices [B*N*Q] ++ quantized [B*N*D] ++ commits [Q]

#define TOKENS   32768
#define DDIM     128
#define NCH      32          // float4 chunks per row
#define KCODES   1024
#define QSTAGES  8
#define BM       128
#define BKT      128
#define NTHREADS 256
#define NBLOCKS  (TOKENS / BM)   // 256

__device__ float g_res[TOKENS * DDIM];
__device__ float g_c2[QSTAGES * KCODES];
__device__ float g_partial[QSTAGES * NBLOCKS];

// ---------------------------------------------------------------------------
__device__ __forceinline__ void cp16(uint32_t dst, const void* src) {
    asm volatile("cp.async.cg.shared.global [%0], [%1], 16;" :: "r"(dst), "l"(src));
}
__device__ __forceinline__ void cp_commit() { asm volatile("cp.async.commit_group;"); }
template<int N> __device__ __forceinline__ void cp_wait() {
    asm volatile("cp.async.wait_group %0;" :: "n"(N) : "memory");
}

// ---------------------------------------------------------------------------
// ||c||^2 for all Q*K codes. One warp per code.
// ---------------------------------------------------------------------------
__global__ void c2_kernel(const float* __restrict__ cb) {
    int warp = (blockIdx.x * blockDim.x + threadIdx.x) >> 5;
    int lane = threadIdx.x & 31;
    const float4* row = (const float4*)(cb + (size_t)warp * DDIM);
    float4 v = row[lane];
    float s = v.x * v.x + v.y * v.y + v.z * v.z + v.w * v.w;
    #pragma unroll
    for (int o = 16; o > 0; o >>= 1) s += __shfl_down_sync(0xffffffffu, s, o);
    if (lane == 0) g_c2[warp] = s;
}

// ---------------------------------------------------------------------------
// One RVQ stage. CTA: 128 tokens x 128-code tiles (8 tiles).
// XOR-swizzled smem (chunk c at c ^ ((row>>2)&7)) -> conflict-free LDS.128.
// 8x8 microtile, scalar FFMA, single pass (A fragment loaded once per chunk).
// ---------------------------------------------------------------------------
extern __shared__ float smem[];

__global__ __launch_bounds__(NTHREADS, 1)
void stage_kernel(const float* __restrict__ x,
                  const float* __restrict__ cb_all,
                  float* __restrict__ out,
                  int stage, int is_last) {
    float* As     = smem;                     // [128][128] swizzled  (64 KB)
    float* Bs0    = smem + 16384;             // B tile buffer 0      (64 KB)
    float* Bs1    = smem + 32768;             // B tile buffer 1      (64 KB)
    float* redv   = smem + 49152;             // [16][128]
    int*   redi   = (int*)(smem + 51200);     // [16][128]
    int*   chosen = (int*)(smem + 53248);     // [128]

    const float*  src = (stage == 0) ? x : (const float*)g_res;
    const float*  cb  = cb_all + (size_t)stage * KCODES * DDIM;
    const float4* cb4 = (const float4*)cb;
    const float*  c2  = g_c2 + stage * KCODES;

    const int tid  = threadIdx.x;
    const int tok0 = blockIdx.x * BM;
    const int lane = tid & 31, wid = tid >> 5;
    const int warp_t = wid & 1, warp_c = wid >> 1;   // 2 x 4 warp grid
    const int t8 = lane & 7, c4 = lane >> 3;         // 8 x 4 lane grid

    // ---- async fill: A tile + B tile 0 (swizzled destinations) ----
    {
        const float4* s4  = (const float4*)src + (size_t)tok0 * NCH;
        uint32_t asb = (uint32_t)__cvta_generic_to_shared(As);
        uint32_t bsb = (uint32_t)__cvta_generic_to_shared(Bs0);
        #pragma unroll
        for (int k = 0; k < 16; k++) {
            int f = tid + k * NTHREADS;
            int t = f >> 5, c = f & 31;
            int sw = c ^ ((t >> 2) & 7);
            cp16(asb + (uint32_t)(t * 512 + sw * 16), s4 + t * NCH + c);
            cp16(bsb + (uint32_t)(t * 512 + sw * 16), cb4 + t * NCH + c);
        }
        cp_commit();
    }

    // per-thread rows: 8 tokens (tl), 8 codes (cloc, ascending)
    int tl[8];
    const float* aRow[8];
    #pragma unroll
    for (int i = 0; i < 8; i++) {
        tl[i] = warp_t * 64 + t8 * 4 + (i < 4 ? i : 28 + i);   // +0..3 / +32..35
        aRow[i] = As + tl[i] * DDIM;
    }
    const int cloc0 = warp_c * 32 + c4 * 8;   // thread's 8 codes: cloc0..cloc0+7

    float best[8]; int bidx[8];
    #pragma unroll
    for (int i = 0; i < 8; i++) { best[i] = 3.4e38f; bidx[i] = 0; }

    for (int kt = 0; kt < KCODES / BKT; kt++) {
        __syncthreads();   // everyone done with the buffer about to be refilled
        if (kt + 1 < KCODES / BKT) {
            float* Bn = ((kt + 1) & 1) ? Bs1 : Bs0;
            uint32_t bsb = (uint32_t)__cvta_generic_to_shared(Bn);
            const float4* bsrc = cb4 + (size_t)(kt + 1) * BKT * NCH;
            #pragma unroll
            for (int k = 0; k < 16; k++) {
                int f = tid + k * NTHREADS;
                int t = f >> 5, c = f & 31;
                int sw = c ^ ((t >> 2) & 7);
                cp16(bsb + (uint32_t)(t * 512 + sw * 16), bsrc + t * NCH + c);
            }
            cp_commit();
            cp_wait<1>();   // current B tile (and A) ready
        } else {
            cp_wait<0>();
        }
        __syncthreads();

        const float* Bt = (kt & 1) ? Bs1 : Bs0;
        const float* bRow[8];
        #pragma unroll
        for (int j = 0; j < 8; j++) bRow[j] = Bt + (cloc0 + j) * DDIM;

        // prefetch ||c||^2 for this tile's 8 codes (2x float4, L2-hit)
        float4 cc0 = __ldg((const float4*)(c2 + kt * BKT + cloc0));
        float4 cc1 = __ldg((const float4*)(c2 + kt * BKT + cloc0 + 4));

        float acc[8][8];
        #pragma unroll
        for (int i = 0; i < 8; i++)
            #pragma unroll
            for (int j = 0; j < 8; j++) acc[i][j] = 0.f;

        #pragma unroll 2
        for (int d4 = 0; d4 < NCH; d4++) {
            const int offA = (d4 ^ t8) << 2;            // float offset in A row
            float4 a[8];
            #pragma unroll
            for (int i = 0; i < 8; i++)
                a[i] = *(const float4*)(aRow[i] + offA);

            #pragma unroll
            for (int jh = 0; jh < 2; jh++) {
                const int offB = (d4 ^ (c4 * 2 + jh)) << 2;
                float4 b[4];
                #pragma unroll
                for (int jj = 0; jj < 4; jj++)
                    b[jj] = *(const float4*)(bRow[jh * 4 + jj] + offB);
                #pragma unroll
                for (int i = 0; i < 8; i++)
                    #pragma unroll
                    for (int jj = 0; jj < 4; jj++) {
                        float s = acc[i][jh * 4 + jj];
                        s += a[i].x * b[jj].x;
                        s += a[i].y * b[jj].y;
                        s += a[i].z * b[jj].z;
                        s += a[i].w * b[jj].w;
                        acc[i][jh * 4 + jj] = s;
                    }
            }
        }

        // running argmin, ascending code order (first-occurrence semantics)
        float ccv[8] = {cc0.x, cc0.y, cc0.z, cc0.w, cc1.x, cc1.y, cc1.z, cc1.w};
        #pragma unroll
        for (int j = 0; j < 8; j++) {
            int code = kt * BKT + cloc0 + j;
            #pragma unroll
            for (int i = 0; i < 8; i++) {
                float dd = ccv[j] - 2.f * acc[i][j];
                if (dd < best[i]) { best[i] = dd; bidx[i] = code; }
            }
        }
    }

    // ---- cross-thread argmin reduction (16 contributors per token) ----
    __syncthreads();
    const int contrib = warp_c * 4 + c4;   // 0..15
    #pragma unroll
    for (int i = 0; i < 8; i++) {
        redv[contrib * 128 + tl[i]] = best[i];
        redi[contrib * 128 + tl[i]] = bidx[i];
    }
    __syncthreads();
    if (tid < BM) {
        float bv = redv[tid];
        int   bi = redi[tid];
        #pragma unroll
        for (int c = 1; c < 16; c++) {
            float v  = redv[c * 128 + tid];
            int   ci = redi[c * 128 + tid];
            if (v < bv || (v == bv && ci < bi)) { bv = v; bi = ci; }
        }
        chosen[tid] = bi;
        out[(size_t)(tok0 + tid) * QSTAGES + stage] = (float)bi;
    }
    __syncthreads();

    // ---- residual update + commit partial + optional quantized output ----
    float4*       res4 = (float4*)g_res + (size_t)tok0 * NCH;
    const float4* x4   = (const float4*)x + (size_t)tok0 * NCH;
    float4*       q4   = (float4*)(out + (size_t)TOKENS * QSTAGES) + (size_t)tok0 * NCH;

    float psum = 0.f;
    #pragma unroll
    for (int k = 0; k < 16; k++) {
        int f = tid + k * NTHREADS;
        int t = f >> 5, d4 = f & 31;
        int sw = d4 ^ ((t >> 2) & 7);
        float4 rv = *(const float4*)(As + t * DDIM + sw * 4);
        int kk = chosen[t];
        float4 cv = cb4[(size_t)kk * NCH + d4];
        float4 nv = make_float4(rv.x - cv.x, rv.y - cv.y, rv.z - cv.z, rv.w - cv.w);
        res4[t * NCH + d4] = nv;
        psum += nv.x * nv.x + nv.y * nv.y + nv.z * nv.z + nv.w * nv.w;
        if (is_last) {
            float4 xv = x4[t * NCH + d4];
            q4[t * NCH + d4] = make_float4(xv.x - nv.x, xv.y - nv.y,
                                           xv.z - nv.z, xv.w - nv.w);
        }
    }
    int ln = tid & 31, w = tid >> 5;
    #pragma unroll
    for (int o = 16; o > 0; o >>= 1) psum += __shfl_down_sync(0xffffffffu, psum, o);
    if (ln == 0) redv[w] = psum;
    __syncthreads();
    if (tid == 0) {
        float s = 0.f;
        #pragma unroll
        for (int w2 = 0; w2 < 8; w2++) s += redv[w2];
        g_partial[stage * NBLOCKS + blockIdx.x] = s;
    }
}

// ---------------------------------------------------------------------------
__global__ void finish_kernel(float* __restrict__ out) {
    int q = threadIdx.x;
    if (q < QSTAGES) {
        float s = 0.f;
        for (int b = 0; b < NBLOCKS; b++) s += g_partial[q * NBLOCKS + b];
        out[(size_t)TOKENS * QSTAGES + (size_t)TOKENS * DDIM + q] =
            s / (float)(TOKENS * DDIM);
    }
}

extern "C" void kernel_launch(void* const* d_in, const int* in_sizes, int n_in,
                              void* d_out, int out_size) {
    const float* x  = (const float*)d_in[0];
    const float* cb = (const float*)d_in[1];
    float* out = (float*)d_out;

    size_t shmem = (size_t)(53248 + 128) * sizeof(float);   // 213504 B
    cudaFuncSetAttribute(stage_kernel,
                         cudaFuncAttributeMaxDynamicSharedMemorySize, (int)shmem);

    c2_kernel<<<1024, 256>>>(cb);
    for (int s = 0; s < QSTAGES; s++) {
        stage_kernel<<<NBLOCKS, NTHREADS, shmem>>>(x, cb, out, s,
                                                   (s == QSTAGES - 1) ? 1 : 0);
    }
    finish_kernel<<<1, 32>>>(out);
}